// round 4
// baseline (speedup 1.0000x reference)
#include <cuda_runtime.h>
#include <cuda_fp16.h>
#include <stdint.h>

#define B_  32
#define S_  512
#define D_  2048
#define MTOT (B_*S_)          // 16384 rows
#define NTILES 8              // 2048/256 n-tiles

// ---------------- device scratch (no allocations allowed) ----------------
__device__ __align__(16) __half g_xh   [(size_t)MTOT * D_];   // 64 MiB fp16 x [m][k]
__device__ __align__(16) __half g_w1t  [(size_t)D_ * D_];     //  8 MiB fp16 W1^T [n][k]
__device__ __align__(16) float  g_vpart[NTILES * MTOT];       // partial v
__device__ __align__(16) float  g_v    [MTOT];                // v = relu(h)@W2 + b2
__device__ __align__(16) float2 g_G    [MTOT];                // Green diag (re,im)

// ---------------- PTX helpers ----------------
__device__ __forceinline__ uint32_t smem_u32(const void* p){
    return (uint32_t)__cvta_generic_to_shared(p);
}
__device__ __forceinline__ void cp16(void* s, const void* g){
    asm volatile("cp.async.cg.shared.global [%0], [%1], 16;\n"
                 :: "r"(smem_u32(s)), "l"(g));
}
__device__ __forceinline__ void cp_commit(){ asm volatile("cp.async.commit_group;\n"::); }
template<int N> __device__ __forceinline__ void cp_wait(){
    asm volatile("cp.async.wait_group %0;\n" :: "n"(N));
}
__device__ __forceinline__ void ldsm_x4(uint32_t r[4], uint32_t addr){
    asm volatile("ldmatrix.sync.aligned.m8n8.x4.shared.b16 {%0,%1,%2,%3}, [%4];\n"
                 : "=r"(r[0]), "=r"(r[1]), "=r"(r[2]), "=r"(r[3]) : "r"(addr));
}
__device__ __forceinline__ void mma16816(float c[4], const uint32_t a[4],
                                         uint32_t b0, uint32_t b1){
    asm volatile(
      "mma.sync.aligned.m16n8k16.row.col.f32.f16.f16.f32 "
      "{%0,%1,%2,%3},{%4,%5,%6,%7},{%8,%9},{%0,%1,%2,%3};\n"
      : "+f"(c[0]), "+f"(c[1]), "+f"(c[2]), "+f"(c[3])
      : "r"(a[0]), "r"(a[1]), "r"(a[2]), "r"(a[3]), "r"(b0), "r"(b1));
}

// ---------------- kernel 0a: fp32 -> fp16 conversion of x ----------------
__global__ void convert_x_kernel(const float* __restrict__ x){
    int i = blockIdx.x * blockDim.x + threadIdx.x;   // over MTOT*D_/4
    float4 f = reinterpret_cast<const float4*>(x)[i];
    __half2* o = reinterpret_cast<__half2*>(g_xh);
    o[2*i]   = __floats2half2_rn(f.x, f.y);
    o[2*i+1] = __floats2half2_rn(f.z, f.w);
}

// ---------------- kernel 0b: W1 [K][N] fp32 -> W1^T [N][K] fp16 ----------------
__global__ void transpose_w1_kernel(const float* __restrict__ w1){
    __shared__ float t[32][33];
    const int bx = blockIdx.x * 32;   // n tile
    const int by = blockIdx.y * 32;   // k tile
    const int tx = threadIdx.x;
    #pragma unroll
    for (int i = threadIdx.y; i < 32; i += 8)
        t[i][tx] = w1[(size_t)(by + i) * D_ + bx + tx];
    __syncthreads();
    #pragma unroll
    for (int i = threadIdx.y; i < 32; i += 8)
        g_w1t[(size_t)(bx + i) * D_ + by + tx] = __float2half_rn(t[tx][i]);
}

// ---------------- kernel 1: HMMA GEMM tile 256x256, warp tile 64x64 ------------
// grid = (8 n-tiles, 64 m-tiles); 512 threads = 16 warps as 4(m) x 4(n).
// 4-stage cp.async pipeline, K chunk = 32, one barrier per chunk.
// Both A[m][k] and B=W1^T[n][k] use the same non-trans ldmatrix pattern.
#define AP 40                    // padded row stride in halves (32+8)
#define TILE_HALF (256*AP)       // halves per (A or B) tile per stage
#define STG_HALF  (2*TILE_HALF)
#define NSTG 4
#define SMEM_BYTES (NSTG*STG_HALF*2 + 256*4)
#define NK 64                    // 2048/32 k-chunks

__global__ void __launch_bounds__(512, 1)
gemm_v_kernel(const float* __restrict__ b1, const float* __restrict__ w2)
{
    extern __shared__ char smem_raw[];
    __half* sm = reinterpret_cast<__half*>(smem_raw);               // [4][2][256][AP]
    float*  vsm = reinterpret_cast<float*>(smem_raw + NSTG*STG_HALF*2);  // [256]

    const int tid  = threadIdx.x;
    const int lane = tid & 31;
    const int warp = tid >> 5;
    const int wm   = warp >> 2;     // 0..3
    const int wn   = warp & 3;      // 0..3
    const int nb    = blockIdx.x * 256;
    const size_t mbase = (size_t)blockIdx.y * 256;

    if (tid < 256) vsm[tid] = 0.0f;

    const __half* Ag = g_xh  + mbase * D_;
    const __half* Bg = g_w1t + (size_t)nb * D_;

    // per-stage loader: A 256x32 + B 256x32 halves; 2+2 chunks of 16B per thread
    auto load_stage = [&](int s, int kt){
        __half* sa = sm + s * STG_HALF;
        __half* sb = sa + TILE_HALF;
        #pragma unroll
        for (int i = 0; i < 2; i++){
            int id = tid + i * 512;
            int r = id >> 2, c = id & 3;
            cp16(sa + r*AP + c*8, Ag + (size_t)r*D_ + kt*32 + c*8);
        }
        #pragma unroll
        for (int i = 0; i < 2; i++){
            int id = tid + i * 512;
            int r = id >> 2, c = id & 3;
            cp16(sb + r*AP + c*8, Bg + (size_t)r*D_ + kt*32 + c*8);
        }
    };

    float acc[4][8][4];
    #pragma unroll
    for (int mi = 0; mi < 4; mi++)
        #pragma unroll
        for (int j = 0; j < 8; j++)
            #pragma unroll
            for (int r = 0; r < 4; r++) acc[mi][j][r] = 0.0f;

    load_stage(0, 0); cp_commit();
    load_stage(1, 1); cp_commit();
    load_stage(2, 2); cp_commit();

    const int lrow = lane & 15;
    const int lcol = (lane >> 4) * 8;

    for (int kt = 0; kt < NK; kt++){
        if (kt < NK-2)       cp_wait<2>();
        else if (kt == NK-2) cp_wait<1>();
        else                 cp_wait<0>();
        __syncthreads();

        const __half* sa = sm + (kt & 3) * STG_HALF;
        const __half* sb = sa + TILE_HALF;

        #pragma unroll
        for (int ks = 0; ks < 2; ks++){
            uint32_t af[4][4];
            #pragma unroll
            for (int mi = 0; mi < 4; mi++)
                ldsm_x4(af[mi], smem_u32(sa + (wm*64 + mi*16 + lrow)*AP + ks*16 + lcol));
            uint32_t bf[4][4];
            #pragma unroll
            for (int ng = 0; ng < 4; ng++)
                ldsm_x4(bf[ng], smem_u32(sb + (wn*64 + ng*16 + lrow)*AP + ks*16 + lcol));
            #pragma unroll
            for (int mi = 0; mi < 4; mi++)
                #pragma unroll
                for (int ng = 0; ng < 4; ng++){
                    mma16816(acc[mi][2*ng+0], af[mi], bf[ng][0], bf[ng][2]);
                    mma16816(acc[mi][2*ng+1], af[mi], bf[ng][1], bf[ng][3]);
                }
        }

        if (kt + 3 < NK){
            load_stage((kt + 3) & 3, kt + 3);
            cp_commit();
        }
        // stage being overwritten was released by this iteration's __syncthreads()
    }

    // ---------------- epilogue: bias + relu + dot(W2) partial ----------------
    #pragma unroll
    for (int mi = 0; mi < 4; mi++){
        float s0 = 0.0f, s1 = 0.0f;   // rows (lane>>2) and (lane>>2)+8
        #pragma unroll
        for (int j = 0; j < 8; j++){
            int col = nb + wn*64 + j*8 + (lane & 3)*2;
            float bb0 = b1[col], bb1 = b1[col+1];
            float ww0 = w2[col], ww1 = w2[col+1];
            s0 += fmaxf(acc[mi][j][0] + bb0, 0.0f) * ww0;
            s0 += fmaxf(acc[mi][j][1] + bb1, 0.0f) * ww1;
            s1 += fmaxf(acc[mi][j][2] + bb0, 0.0f) * ww0;
            s1 += fmaxf(acc[mi][j][3] + bb1, 0.0f) * ww1;
        }
        s0 += __shfl_xor_sync(0xffffffffu, s0, 1);
        s0 += __shfl_xor_sync(0xffffffffu, s0, 2);
        s1 += __shfl_xor_sync(0xffffffffu, s1, 1);
        s1 += __shfl_xor_sync(0xffffffffu, s1, 2);
        if ((lane & 3) == 0){
            int row = wm*64 + mi*16 + (lane >> 2);
            atomicAdd(&vsm[row],     s0);
            atomicAdd(&vsm[row + 8], s1);
        }
    }
    __syncthreads();
    if (tid < 256)
        g_vpart[(size_t)blockIdx.x * MTOT + mbase + tid] = vsm[tid];
}

// ---------------- kernel 1b: reduce partials -> v ----------------
__global__ void v_reduce_kernel(const float* __restrict__ b2){
    int i = blockIdx.x * blockDim.x + threadIdx.x;  // over MTOT
    float s = b2[0];
    #pragma unroll
    for (int nt = 0; nt < NTILES; nt++)
        s += g_vpart[(size_t)nt * MTOT + i];
    g_v[i] = s;
}

// ---------------- kernel 2: Green's function diagonal ----------------
// Stable continued fractions: p_i = 1/(a_{i-1}-p_{i-1}), q_i = 1/(a_{i+1}-q_{i+1}),
// G_ii = 1/(a_i - p_i - q_i), a_i = (v_i - 2) - 1j. |Im(denominator)| >= 1 always.
__global__ void green_kernel(){
    __shared__ float  vsm[S_];
    __shared__ float2 ps[S_];
    __shared__ float2 qs[S_];
    const int b = blockIdx.x;
    const int tid = threadIdx.x;
    for (int i = tid; i < S_; i += blockDim.x) vsm[i] = g_v[b * S_ + i];
    __syncthreads();

    if (tid == 0){
        float pr = 0.0f, pi = 0.0f;
        ps[0] = make_float2(0.0f, 0.0f);
        #pragma unroll 4
        for (int i = 1; i < S_; i++){
            float wr = (vsm[i-1] - 2.0f) - pr;
            float wi = -1.0f - pi;
            float inv = 1.0f / (wr*wr + wi*wi);
            pr =  wr * inv;
            pi = -wi * inv;
            ps[i] = make_float2(pr, pi);
        }
    } else if (tid == 32){
        float qr = 0.0f, qi = 0.0f;
        qs[S_-1] = make_float2(0.0f, 0.0f);
        #pragma unroll 4
        for (int i = S_-2; i >= 0; i--){
            float wr = (vsm[i+1] - 2.0f) - qr;
            float wi = -1.0f - qi;
            float inv = 1.0f / (wr*wr + wi*wi);
            qr =  wr * inv;
            qi = -wi * inv;
            qs[i] = make_float2(qr, qi);
        }
    }
    __syncthreads();
    for (int i = tid; i < S_; i += blockDim.x){
        float wr = (vsm[i] - 2.0f) - ps[i].x - qs[i].x;
        float wi = -1.0f           - ps[i].y - qs[i].y;
        float inv = 1.0f / (wr*wr + wi*wi);
        g_G[b*S_ + i] = make_float2(wr*inv, -wi*inv);
    }
}

// ---------------- kernel 3: out = Gr*Wp[0,:] + Gi*Wp[1,:] + bp ----------------
__global__ void out_kernel(const float* __restrict__ Wp, const float* __restrict__ bp,
                           float* __restrict__ out){
    int i = blockIdx.x * blockDim.x + threadIdx.x;   // over (MTOT/4)*512
    int c4   = i & 511;
    int row0 = (i >> 9) << 2;
    float4 w0 = reinterpret_cast<const float4*>(Wp)[c4];
    float4 w1 = reinterpret_cast<const float4*>(Wp + D_)[c4];
    float4 bb = reinterpret_cast<const float4*>(bp)[c4];
    #pragma unroll
    for (int r = 0; r < 4; r++){
        float2 G = g_G[row0 + r];
        float4 o;
        o.x = G.x*w0.x + G.y*w1.x + bb.x;
        o.y = G.x*w0.y + G.y*w1.y + bb.y;
        o.z = G.x*w0.z + G.y*w1.z + bb.z;
        o.w = G.x*w0.w + G.y*w1.w + bb.w;
        __stcs(reinterpret_cast<float4*>(out) + (size_t)(row0 + r) * 512 + c4, o);
    }
}

// ---------------- launch ----------------
extern "C" void kernel_launch(void* const* d_in, const int* in_sizes, int n_in,
                              void* d_out, int out_size)
{
    const float* x  = (const float*)d_in[0];
    const float* W1 = (const float*)d_in[1];
    const float* b1 = (const float*)d_in[2];
    const float* W2 = (const float*)d_in[3];
    const float* b2 = (const float*)d_in[4];
    const float* Wp = (const float*)d_in[5];
    const float* bp = (const float*)d_in[6];
    float* out = (float*)d_out;

    convert_x_kernel<<<(MTOT*(D_/4))/256, 256>>>(x);
    transpose_w1_kernel<<<dim3(D_/32, D_/32), dim3(32, 8)>>>(W1);

    cudaFuncSetAttribute(gemm_v_kernel, cudaFuncAttributeMaxDynamicSharedMemorySize, SMEM_BYTES);
    gemm_v_kernel<<<dim3(NTILES, MTOT/256), 512, SMEM_BYTES>>>(b1, W2);
    v_reduce_kernel<<<MTOT/256, 256>>>(b2);

    green_kernel<<<B_, 64>>>();
    out_kernel<<<(MTOT/4*512)/256, 256>>>(Wp, bp, out);
}

// round 5
// speedup vs baseline: 2.2843x; 2.2843x over previous
#include <cuda_runtime.h>
#include <cuda_fp16.h>
#include <stdint.h>

#define B_  32
#define S_  512
#define D_  2048
#define MTOT (B_*S_)          // 16384 rows
#define NTILES 16             // 2048/128 n-tiles

// ---------------- device scratch (no allocations allowed) ----------------
__device__ __align__(16) __half g_xh   [(size_t)MTOT * D_];   // 64 MiB fp16 x [m][k]
__device__ __align__(16) __half g_w1t  [(size_t)D_ * D_];     //  8 MiB fp16 W1^T [n][k]
__device__ __align__(16) float  g_vpart[NTILES * MTOT];       // partial v
__device__ __align__(16) float2 g_G    [MTOT];                // Green diag (re,im)

// ---------------- PTX helpers ----------------
__device__ __forceinline__ uint32_t smem_u32(const void* p){
    return (uint32_t)__cvta_generic_to_shared(p);
}
__device__ __forceinline__ void cp16(void* s, const void* g){
    asm volatile("cp.async.cg.shared.global [%0], [%1], 16;\n"
                 :: "r"(smem_u32(s)), "l"(g));
}
__device__ __forceinline__ void cp_commit(){ asm volatile("cp.async.commit_group;\n"::); }
template<int N> __device__ __forceinline__ void cp_wait(){
    asm volatile("cp.async.wait_group %0;\n" :: "n"(N));
}
__device__ __forceinline__ void ldsm_x4(uint32_t r[4], uint32_t addr){
    asm volatile("ldmatrix.sync.aligned.m8n8.x4.shared.b16 {%0,%1,%2,%3}, [%4];\n"
                 : "=r"(r[0]), "=r"(r[1]), "=r"(r[2]), "=r"(r[3]) : "r"(addr));
}
__device__ __forceinline__ void mma16816(float c[4], const uint32_t a[4],
                                         uint32_t b0, uint32_t b1){
    asm volatile(
      "mma.sync.aligned.m16n8k16.row.col.f32.f16.f16.f32 "
      "{%0,%1,%2,%3},{%4,%5,%6,%7},{%8,%9},{%0,%1,%2,%3};\n"
      : "+f"(c[0]), "+f"(c[1]), "+f"(c[2]), "+f"(c[3])
      : "r"(a[0]), "r"(a[1]), "r"(a[2]), "r"(a[3]), "r"(b0), "r"(b1));
}

// ---------------- kernel 0a: fp32 -> fp16 conversion of x ----------------
__global__ void convert_x_kernel(const float* __restrict__ x){
    int i = blockIdx.x * blockDim.x + threadIdx.x;   // over MTOT*D_/4
    float4 f = reinterpret_cast<const float4*>(x)[i];
    __half2* o = reinterpret_cast<__half2*>(g_xh);
    o[2*i]   = __floats2half2_rn(f.x, f.y);
    o[2*i+1] = __floats2half2_rn(f.z, f.w);
}

// ---------------- kernel 0b: W1 [K][N] fp32 -> W1^T [N][K] fp16 ----------------
__global__ void transpose_w1_kernel(const float* __restrict__ w1){
    __shared__ float t[32][33];
    const int bx = blockIdx.x * 32;   // n tile
    const int by = blockIdx.y * 32;   // k tile
    const int tx = threadIdx.x;
    #pragma unroll
    for (int i = threadIdx.y; i < 32; i += 8)
        t[i][tx] = w1[(size_t)(by + i) * D_ + bx + tx];
    __syncthreads();
    #pragma unroll
    for (int i = threadIdx.y; i < 32; i += 8)
        g_w1t[(size_t)(bx + i) * D_ + by + tx] = __float2half_rn(t[tx][i]);
}

// ---------------- kernel 1: HMMA GEMM tile 128x128, warp 64x32 -----------------
// grid = (16 n-tiles, 128 m-tiles); 256 threads = 8 warps as 2(m) x 4(n).
// 3-stage cp.async pipeline, K chunk = 64 (one barrier per 64-K chunk).
// A[m][k] and B=W1^T[n][k] use the same non-trans ldmatrix pattern.
#define AP 72                    // padded row stride in halves (64+8)
#define TILE_HALF (128*AP)       // halves per (A or B) tile per stage
#define STG_HALF  (2*TILE_HALF)
#define NSTG 3
#define SMEM_BYTES (NSTG*STG_HALF*2 + 128*4)
#define NK 32                    // 2048/64 k-chunks

__global__ void __launch_bounds__(256, 2)
gemm_v_kernel(const float* __restrict__ b1, const float* __restrict__ w2)
{
    extern __shared__ char smem_raw[];
    __half* sm = reinterpret_cast<__half*>(smem_raw);               // [3][2][128][AP]
    float*  vsm = reinterpret_cast<float*>(smem_raw + NSTG*STG_HALF*2);  // [128]

    const int tid  = threadIdx.x;
    const int lane = tid & 31;
    const int warp = tid >> 5;
    const int wm   = warp >> 2;     // 0..1
    const int wn   = warp & 3;      // 0..3
    const int nb    = blockIdx.x * 128;
    const size_t mbase = (size_t)blockIdx.y * 128;

    if (tid < 128) vsm[tid] = 0.0f;

    const __half* Ag = g_xh  + mbase * D_;
    const __half* Bg = g_w1t + (size_t)nb * D_;

    // per-stage loader: A 128x64 + B 128x64 halves; 4+4 chunks of 16B per thread
    auto load_stage = [&](int s, int kt){
        __half* sa = sm + s * STG_HALF;
        __half* sb = sa + TILE_HALF;
        #pragma unroll
        for (int i = 0; i < 4; i++){
            int id = tid + i * 256;
            int r = id >> 3, c = id & 7;
            cp16(sa + r*AP + c*8, Ag + (size_t)r*D_ + kt*64 + c*8);
        }
        #pragma unroll
        for (int i = 0; i < 4; i++){
            int id = tid + i * 256;
            int r = id >> 3, c = id & 7;
            cp16(sb + r*AP + c*8, Bg + (size_t)r*D_ + kt*64 + c*8);
        }
    };

    float acc[4][4][4];
    #pragma unroll
    for (int mi = 0; mi < 4; mi++)
        #pragma unroll
        for (int j = 0; j < 4; j++)
            #pragma unroll
            for (int r = 0; r < 4; r++) acc[mi][j][r] = 0.0f;

    load_stage(0, 0); cp_commit();
    load_stage(1, 1); cp_commit();

    const int lrow = lane & 15;
    const int lcol = (lane >> 4) * 8;

    for (int kt = 0; kt < NK; kt++){
        if (kt < NK-1) cp_wait<1>();
        else           cp_wait<0>();
        __syncthreads();

        int s = kt % 3;
        const __half* sa = sm + s * STG_HALF;
        const __half* sb = sa + TILE_HALF;

        #pragma unroll
        for (int ks = 0; ks < 4; ks++){
            uint32_t af[4][4];
            #pragma unroll
            for (int mi = 0; mi < 4; mi++)
                ldsm_x4(af[mi], smem_u32(sa + (wm*64 + mi*16 + lrow)*AP + ks*16 + lcol));
            uint32_t bf[2][4];
            #pragma unroll
            for (int bg = 0; bg < 2; bg++)
                ldsm_x4(bf[bg], smem_u32(sb + (wn*32 + bg*16 + lrow)*AP + ks*16 + lcol));
            #pragma unroll
            for (int mi = 0; mi < 4; mi++)
                #pragma unroll
                for (int bg = 0; bg < 2; bg++){
                    mma16816(acc[mi][bg*2+0], af[mi], bf[bg][0], bf[bg][2]);
                    mma16816(acc[mi][bg*2+1], af[mi], bf[bg][1], bf[bg][3]);
                }
        }

        if (kt + 2 < NK){
            int s2 = (kt + 2) % 3;     // == (kt-1)%3, released by this kt's barrier
            load_stage(s2, kt + 2);
            cp_commit();
        }
    }

    // ---------------- epilogue: bias + relu + dot(W2) partial ----------------
    #pragma unroll
    for (int mi = 0; mi < 4; mi++){
        float s0 = 0.0f, s1 = 0.0f;   // rows (lane>>2) and (lane>>2)+8
        #pragma unroll
        for (int j = 0; j < 4; j++){
            int col = nb + wn*32 + j*8 + (lane & 3)*2;
            float bb0 = b1[col], bb1 = b1[col+1];
            float ww0 = w2[col], ww1 = w2[col+1];
            s0 += fmaxf(acc[mi][j][0] + bb0, 0.0f) * ww0;
            s0 += fmaxf(acc[mi][j][1] + bb1, 0.0f) * ww1;
            s1 += fmaxf(acc[mi][j][2] + bb0, 0.0f) * ww0;
            s1 += fmaxf(acc[mi][j][3] + bb1, 0.0f) * ww1;
        }
        s0 += __shfl_xor_sync(0xffffffffu, s0, 1);
        s0 += __shfl_xor_sync(0xffffffffu, s0, 2);
        s1 += __shfl_xor_sync(0xffffffffu, s1, 1);
        s1 += __shfl_xor_sync(0xffffffffu, s1, 2);
        if ((lane & 3) == 0){
            int row = wm*64 + mi*16 + (lane >> 2);
            atomicAdd(&vsm[row],     s0);
            atomicAdd(&vsm[row + 8], s1);
        }
    }
    __syncthreads();
    if (tid < 128)
        g_vpart[(size_t)blockIdx.x * MTOT + mbase + tid] = vsm[tid];
}

// ---------------- kernel 2: reduce partials + Green's function diagonal --------
// v_i = b2 + sum_nt vpart; then stable continued fractions:
// p_i = 1/(a_{i-1}-p_{i-1}), q_i = 1/(a_{i+1}-q_{i+1}), G_ii = 1/(a_i - p_i - q_i),
// a_i = (v_i - 2) - 1j.  |Im(denominator)| >= 1 always.
__global__ void green_kernel(const float* __restrict__ b2){
    __shared__ float  vsm[S_];
    __shared__ float2 ps[S_];
    __shared__ float2 qs[S_];
    const int b = blockIdx.x;
    const int tid = threadIdx.x;
    const float bias2 = b2[0];
    for (int i = tid; i < S_; i += blockDim.x){
        float s = bias2;
        #pragma unroll
        for (int nt = 0; nt < NTILES; nt++)
            s += g_vpart[(size_t)nt * MTOT + b * S_ + i];
        vsm[i] = s;
    }
    __syncthreads();

    if (tid == 0){
        float pr = 0.0f, pi = 0.0f;
        ps[0] = make_float2(0.0f, 0.0f);
        #pragma unroll 4
        for (int i = 1; i < S_; i++){
            float wr = (vsm[i-1] - 2.0f) - pr;
            float wi = -1.0f - pi;
            float inv = 1.0f / (wr*wr + wi*wi);
            pr =  wr * inv;
            pi = -wi * inv;
            ps[i] = make_float2(pr, pi);
        }
    } else if (tid == 32){
        float qr = 0.0f, qi = 0.0f;
        qs[S_-1] = make_float2(0.0f, 0.0f);
        #pragma unroll 4
        for (int i = S_-2; i >= 0; i--){
            float wr = (vsm[i+1] - 2.0f) - qr;
            float wi = -1.0f - qi;
            float inv = 1.0f / (wr*wr + wi*wi);
            qr =  wr * inv;
            qi = -wi * inv;
            qs[i] = make_float2(qr, qi);
        }
    }
    __syncthreads();
    for (int i = tid; i < S_; i += blockDim.x){
        float wr = (vsm[i] - 2.0f) - ps[i].x - qs[i].x;
        float wi = -1.0f           - ps[i].y - qs[i].y;
        float inv = 1.0f / (wr*wr + wi*wi);
        g_G[b*S_ + i] = make_float2(wr*inv, -wi*inv);
    }
}

// ---------------- kernel 3: out = Gr*Wp[0,:] + Gi*Wp[1,:] + bp ----------------
__global__ void out_kernel(const float* __restrict__ Wp, const float* __restrict__ bp,
                           float* __restrict__ out){
    int i = blockIdx.x * blockDim.x + threadIdx.x;   // over (MTOT/4)*512
    int c4   = i & 511;
    int row0 = (i >> 9) << 2;
    float4 w0 = reinterpret_cast<const float4*>(Wp)[c4];
    float4 w1 = reinterpret_cast<const float4*>(Wp + D_)[c4];
    float4 bb = reinterpret_cast<const float4*>(bp)[c4];
    #pragma unroll
    for (int r = 0; r < 4; r++){
        float2 G = g_G[row0 + r];
        float4 o;
        o.x = G.x*w0.x + G.y*w1.x + bb.x;
        o.y = G.x*w0.y + G.y*w1.y + bb.y;
        o.z = G.x*w0.z + G.y*w1.z + bb.z;
        o.w = G.x*w0.w + G.y*w1.w + bb.w;
        __stcs(reinterpret_cast<float4*>(out) + (size_t)(row0 + r) * 512 + c4, o);
    }
}

// ---------------- launch ----------------
extern "C" void kernel_launch(void* const* d_in, const int* in_sizes, int n_in,
                              void* d_out, int out_size)
{
    const float* x  = (const float*)d_in[0];
    const float* W1 = (const float*)d_in[1];
    const float* b1 = (const float*)d_in[2];
    const float* W2 = (const float*)d_in[3];
    const float* b2 = (const float*)d_in[4];
    const float* Wp = (const float*)d_in[5];
    const float* bp = (const float*)d_in[6];
    float* out = (float*)d_out;

    convert_x_kernel<<<(MTOT*(D_/4))/256, 256>>>(x);
    transpose_w1_kernel<<<dim3(D_/32, D_/32), dim3(32, 8)>>>(W1);

    cudaFuncSetAttribute(gemm_v_kernel, cudaFuncAttributeMaxDynamicSharedMemorySize, SMEM_BYTES);
    gemm_v_kernel<<<dim3(NTILES, MTOT/128), 256, SMEM_BYTES>>>(b1, W2);

    green_kernel<<<B_, 64>>>(b2);
    out_kernel<<<(MTOT/4*512)/256, 256>>>(Wp, bp, out);
}

// round 6
// speedup vs baseline: 2.3124x; 1.0123x over previous
#include <cuda_runtime.h>
#include <cuda_fp16.h>
#include <stdint.h>

#define B_  32
#define S_  512
#define D_  2048
#define MTOT (B_*S_)          // 16384 rows
#define NTILES 16             // 2048/128 n-tiles

// ---------------- device scratch (no allocations allowed) ----------------
__device__ __align__(16) __half g_xh   [(size_t)MTOT * D_];   // 64 MiB fp16 x [m][k]
__device__ __align__(16) __half g_w1t  [(size_t)D_ * D_];     //  8 MiB fp16 W1^T [n][k]
__device__ __align__(16) float  g_vpart[NTILES * MTOT];       // partial v
__device__ __align__(16) float2 g_G    [MTOT];                // Green diag (re,im)

// ---------------- PTX helpers ----------------
__device__ __forceinline__ uint32_t smem_u32(const void* p){
    return (uint32_t)__cvta_generic_to_shared(p);
}
__device__ __forceinline__ void cp16(void* s, const void* g){
    asm volatile("cp.async.cg.shared.global [%0], [%1], 16;\n"
                 :: "r"(smem_u32(s)), "l"(g));
}
__device__ __forceinline__ void cp_commit(){ asm volatile("cp.async.commit_group;\n"::); }
template<int N> __device__ __forceinline__ void cp_wait(){
    asm volatile("cp.async.wait_group %0;\n" :: "n"(N));
}
__device__ __forceinline__ void ldsm_x4(uint32_t r[4], uint32_t addr){
    asm volatile("ldmatrix.sync.aligned.m8n8.x4.shared.b16 {%0,%1,%2,%3}, [%4];\n"
                 : "=r"(r[0]), "=r"(r[1]), "=r"(r[2]), "=r"(r[3]) : "r"(addr));
}
__device__ __forceinline__ void mma16816(float c[4], const uint32_t a[4],
                                         uint32_t b0, uint32_t b1){
    asm volatile(
      "mma.sync.aligned.m16n8k16.row.col.f32.f16.f16.f32 "
      "{%0,%1,%2,%3},{%4,%5,%6,%7},{%8,%9},{%0,%1,%2,%3};\n"
      : "+f"(c[0]), "+f"(c[1]), "+f"(c[2]), "+f"(c[3])
      : "r"(a[0]), "r"(a[1]), "r"(a[2]), "r"(a[3]), "r"(b0), "r"(b1));
}
__device__ __forceinline__ float frcp(float x){
    float r; asm("rcp.approx.f32 %0, %1;" : "=f"(r) : "f"(x)); return r;
}

// ---------------- kernel 0a: fp32 -> fp16 conversion of x ----------------
__global__ void convert_x_kernel(const float* __restrict__ x){
    int i = blockIdx.x * blockDim.x + threadIdx.x;   // over MTOT*D_/4
    float4 f = reinterpret_cast<const float4*>(x)[i];
    __half2* o = reinterpret_cast<__half2*>(g_xh);
    o[2*i]   = __floats2half2_rn(f.x, f.y);
    o[2*i+1] = __floats2half2_rn(f.z, f.w);
}

// ---------------- kernel 0b: W1 [K][N] fp32 -> W1^T [N][K] fp16 ----------------
__global__ void transpose_w1_kernel(const float* __restrict__ w1){
    __shared__ float t[32][33];
    const int bx = blockIdx.x * 32;   // n tile
    const int by = blockIdx.y * 32;   // k tile
    const int tx = threadIdx.x;
    #pragma unroll
    for (int i = threadIdx.y; i < 32; i += 8)
        t[i][tx] = w1[(size_t)(by + i) * D_ + bx + tx];
    __syncthreads();
    #pragma unroll
    for (int i = threadIdx.y; i < 32; i += 8)
        g_w1t[(size_t)(bx + i) * D_ + by + tx] = __float2half_rn(t[tx][i]);
}

// ---------------- kernel 1: HMMA GEMM tile 128x128, warp 64x32 -----------------
// grid = (16 n-tiles, 128 m-tiles); 256 threads = 8 warps as 2(m) x 4(n).
// 3-stage cp.async pipeline, K chunk = 64; register double-buffered fragments:
// ldsm for ks+1 issued before the MMAs of ks, hiding LDSM latency.
#define AP 72                    // padded row stride in halves (64+8)
#define TILE_HALF (128*AP)       // halves per (A or B) tile per stage
#define STG_HALF  (2*TILE_HALF)
#define NSTG 3
#define SMEM_BYTES (NSTG*STG_HALF*2 + 128*4)
#define NK 32                    // 2048/64 k-chunks

__global__ void __launch_bounds__(256, 2)
gemm_v_kernel(const float* __restrict__ b1, const float* __restrict__ w2)
{
    extern __shared__ char smem_raw[];
    __half* sm = reinterpret_cast<__half*>(smem_raw);               // [3][2][128][AP]
    float*  vsm = reinterpret_cast<float*>(smem_raw + NSTG*STG_HALF*2);  // [128]

    const int tid  = threadIdx.x;
    const int lane = tid & 31;
    const int warp = tid >> 5;
    const int wm   = warp >> 2;     // 0..1
    const int wn   = warp & 3;      // 0..3
    const int nb    = blockIdx.x * 128;
    const size_t mbase = (size_t)blockIdx.y * 128;

    if (tid < 128) vsm[tid] = 0.0f;

    const __half* Ag = g_xh  + mbase * D_;
    const __half* Bg = g_w1t + (size_t)nb * D_;

    auto load_stage = [&](int s, int kt){
        __half* sa = sm + s * STG_HALF;
        __half* sb = sa + TILE_HALF;
        #pragma unroll
        for (int i = 0; i < 4; i++){
            int id = tid + i * 256;
            int r = id >> 3, c = id & 7;
            cp16(sa + r*AP + c*8, Ag + (size_t)r*D_ + kt*64 + c*8);
        }
        #pragma unroll
        for (int i = 0; i < 4; i++){
            int id = tid + i * 256;
            int r = id >> 3, c = id & 7;
            cp16(sb + r*AP + c*8, Bg + (size_t)r*D_ + kt*64 + c*8);
        }
    };

    float acc[4][4][4];
    #pragma unroll
    for (int mi = 0; mi < 4; mi++)
        #pragma unroll
        for (int j = 0; j < 4; j++)
            #pragma unroll
            for (int r = 0; r < 4; r++) acc[mi][j][r] = 0.0f;

    load_stage(0, 0); cp_commit();
    load_stage(1, 1); cp_commit();

    const int lrow = lane & 15;
    const int lcol = (lane >> 4) * 8;
    const int arow = (wm*64 + lrow) * AP + lcol;   // + mi*16*AP + ks*16
    const int brow = (wn*32 + lrow) * AP + lcol;   // + bg*16*AP + ks*16

    uint32_t af[2][4][4], bf[2][2][4];

    auto load_frags = [&](const __half* sa, const __half* sb, int ks, int buf){
        #pragma unroll
        for (int mi = 0; mi < 4; mi++)
            ldsm_x4(af[buf][mi], smem_u32(sa + arow + mi*16*AP + ks*16));
        #pragma unroll
        for (int bg = 0; bg < 2; bg++)
            ldsm_x4(bf[buf][bg], smem_u32(sb + brow + bg*16*AP + ks*16));
    };

    for (int kt = 0; kt < NK; kt++){
        if (kt < NK-1) cp_wait<1>();
        else           cp_wait<0>();
        __syncthreads();

        int s = kt % 3;
        const __half* sa = sm + s * STG_HALF;
        const __half* sb = sa + TILE_HALF;

        load_frags(sa, sb, 0, 0);

        #pragma unroll
        for (int ks = 0; ks < 4; ks++){
            const int cur = ks & 1;
            if (ks < 3) load_frags(sa, sb, ks + 1, cur ^ 1);
            #pragma unroll
            for (int mi = 0; mi < 4; mi++)
                #pragma unroll
                for (int bg = 0; bg < 2; bg++){
                    mma16816(acc[mi][bg*2+0], af[cur][mi], bf[cur][bg][0], bf[cur][bg][2]);
                    mma16816(acc[mi][bg*2+1], af[cur][mi], bf[cur][bg][1], bf[cur][bg][3]);
                }
        }

        if (kt + 2 < NK){
            int s2 = (kt + 2) % 3;     // == (kt-1)%3, released by this kt's barrier
            load_stage(s2, kt + 2);
            cp_commit();
        }
    }

    // ---------------- epilogue: bias + relu + dot(W2) partial ----------------
    #pragma unroll
    for (int mi = 0; mi < 4; mi++){
        float s0 = 0.0f, s1 = 0.0f;   // rows (lane>>2) and (lane>>2)+8
        #pragma unroll
        for (int j = 0; j < 4; j++){
            int col = nb + wn*32 + j*8 + (lane & 3)*2;
            float bb0 = b1[col], bb1 = b1[col+1];
            float ww0 = w2[col], ww1 = w2[col+1];
            s0 += fmaxf(acc[mi][j][0] + bb0, 0.0f) * ww0;
            s0 += fmaxf(acc[mi][j][1] + bb1, 0.0f) * ww1;
            s1 += fmaxf(acc[mi][j][2] + bb0, 0.0f) * ww0;
            s1 += fmaxf(acc[mi][j][3] + bb1, 0.0f) * ww1;
        }
        s0 += __shfl_xor_sync(0xffffffffu, s0, 1);
        s0 += __shfl_xor_sync(0xffffffffu, s0, 2);
        s1 += __shfl_xor_sync(0xffffffffu, s1, 1);
        s1 += __shfl_xor_sync(0xffffffffu, s1, 2);
        if ((lane & 3) == 0){
            int row = wm*64 + mi*16 + (lane >> 2);
            atomicAdd(&vsm[row],     s0);
            atomicAdd(&vsm[row + 8], s1);
        }
    }
    __syncthreads();
    if (tid < 128)
        g_vpart[(size_t)blockIdx.x * MTOT + mbase + tid] = vsm[tid];
}

// ---------------- kernel 2: reduce partials + Green's function diagonal --------
// v_i = b2 + sum_nt vpart; then stable continued fractions:
// p_i = 1/(a_{i-1}-p_{i-1}), q_i = 1/(a_{i+1}-q_{i+1}), G_ii = 1/(a_i - p_i - q_i),
// a_i = (v_i - 2) - 1j.  |Im(denominator)| >= 1 always -> rcp.approx is safe.
__global__ void green_kernel(const float* __restrict__ b2){
    __shared__ float  vsm[S_];
    __shared__ float2 ps[S_];
    __shared__ float2 qs[S_];
    const int b = blockIdx.x;
    const int tid = threadIdx.x;
    const float bias2 = b2[0];
    for (int i = tid; i < S_; i += blockDim.x){
        float s = bias2;
        #pragma unroll
        for (int nt = 0; nt < NTILES; nt++)
            s += g_vpart[(size_t)nt * MTOT + b * S_ + i];
        vsm[i] = s;
    }
    __syncthreads();

    if (tid == 0){
        float pr = 0.0f, pi = 0.0f;
        ps[0] = make_float2(0.0f, 0.0f);
        #pragma unroll 4
        for (int i = 1; i < S_; i++){
            float wr = (vsm[i-1] - 2.0f) - pr;
            float wi = -1.0f - pi;
            float inv = frcp(wr*wr + wi*wi);
            pr =  wr * inv;
            pi = -wi * inv;
            ps[i] = make_float2(pr, pi);
        }
    } else if (tid == 32){
        float qr = 0.0f, qi = 0.0f;
        qs[S_-1] = make_float2(0.0f, 0.0f);
        #pragma unroll 4
        for (int i = S_-2; i >= 0; i--){
            float wr = (vsm[i+1] - 2.0f) - qr;
            float wi = -1.0f - qi;
            float inv = frcp(wr*wr + wi*wi);
            qr =  wr * inv;
            qi = -wi * inv;
            qs[i] = make_float2(qr, qi);
        }
    }
    __syncthreads();
    for (int i = tid; i < S_; i += blockDim.x){
        float wr = (vsm[i] - 2.0f) - ps[i].x - qs[i].x;
        float wi = -1.0f           - ps[i].y - qs[i].y;
        float inv = 1.0f / (wr*wr + wi*wi);
        g_G[b*S_ + i] = make_float2(wr*inv, -wi*inv);
    }
}

// ---------------- kernel 3: out = Gr*Wp[0,:] + Gi*Wp[1,:] + bp ----------------
__global__ void out_kernel(const float* __restrict__ Wp, const float* __restrict__ bp,
                           float* __restrict__ out){
    int i = blockIdx.x * blockDim.x + threadIdx.x;   // over (MTOT/4)*512
    int c4   = i & 511;
    int row0 = (i >> 9) << 2;
    float4 w0 = reinterpret_cast<const float4*>(Wp)[c4];
    float4 w1 = reinterpret_cast<const float4*>(Wp + D_)[c4];
    float4 bb = reinterpret_cast<const float4*>(bp)[c4];
    #pragma unroll
    for (int r = 0; r < 4; r++){
        float2 G = g_G[row0 + r];
        float4 o;
        o.x = G.x*w0.x + G.y*w1.x + bb.x;
        o.y = G.x*w0.y + G.y*w1.y + bb.y;
        o.z = G.x*w0.z + G.y*w1.z + bb.z;
        o.w = G.x*w0.w + G.y*w1.w + bb.w;
        __stcs(reinterpret_cast<float4*>(out) + (size_t)(row0 + r) * 512 + c4, o);
    }
}

// ---------------- launch ----------------
extern "C" void kernel_launch(void* const* d_in, const int* in_sizes, int n_in,
                              void* d_out, int out_size)
{
    const float* x  = (const float*)d_in[0];
    const float* W1 = (const float*)d_in[1];
    const float* b1 = (const float*)d_in[2];
    const float* W2 = (const float*)d_in[3];
    const float* b2 = (const float*)d_in[4];
    const float* Wp = (const float*)d_in[5];
    const float* bp = (const float*)d_in[6];
    float* out = (float*)d_out;

    convert_x_kernel<<<(MTOT*(D_/4))/256, 256>>>(x);
    transpose_w1_kernel<<<dim3(D_/32, D_/32), dim3(32, 8)>>>(W1);

    cudaFuncSetAttribute(gemm_v_kernel, cudaFuncAttributeMaxDynamicSharedMemorySize, SMEM_BYTES);
    gemm_v_kernel<<<dim3(NTILES, MTOT/128), 256, SMEM_BYTES>>>(b1, W2);

    green_kernel<<<B_, 64>>>(b2);
    out_kernel<<<(MTOT/4*512)/256, 256>>>(Wp, bp, out);
}